// round 2
// baseline (speedup 1.0000x reference)
#include <cuda_runtime.h>

// CoreSageLayer: out[k] = concat((adj@x)/deg, x) @ W[k] + bias
//   N=8192 nodes, F=256, W: [3, 512, 256], out: [3, 8192, 256]
// Stage 1 (sage_agg): x1 = (adj@x)/deg fused with degree rowsum; writes
//                     n_x = [x1 | x] into a __device__ scratch buffer.
// Stage 2 (sage_out): out[k] = n_x @ W[k] + bias, grid.y = 3.
// Both stages use a packed-fp32 (fma.rn.f32x2) 64x256x16 tile microkernel.

#define N_NODES 8192
#define IN_F    256
#define TWO_F   512
#define OUT_F   256

#define BM 64
#define BN 256
#define BK 16
#define NTHREADS 256

// scratch: n_x = [x1/deg | x]  (16 MB, static device allocation)
__device__ float g_nx[(size_t)N_NODES * TWO_F];

// ---------- packed fp32 helpers (Blackwell f32x2 pipe) ----------
__device__ __forceinline__ unsigned long long ffma2(unsigned long long a,
                                                    unsigned long long b,
                                                    unsigned long long c) {
    unsigned long long d;
    asm("fma.rn.f32x2 %0, %1, %2, %3;" : "=l"(d) : "l"(a), "l"(b), "l"(c));
    return d;
}

__device__ __forceinline__ unsigned long long pack2(float lo, float hi) {
    unsigned long long v;
    asm("mov.b64 %0, {%1, %2};" : "=l"(v) : "f"(lo), "f"(hi));
    return v;
}

__device__ __forceinline__ float2 unpack2(unsigned long long v) {
    float2 r;
    asm("mov.b64 {%0, %1}, %2;" : "=f"(r.x), "=f"(r.y) : "l"(v));
    return r;
}

// =================== Stage 1: aggregate + degree ===================
__global__ __launch_bounds__(NTHREADS) void sage_agg(const int* __restrict__ adj,
                                                     const float* __restrict__ x)
{
    // A stored as duplicated f32 pairs (a,a) so the inner loop needs no packs.
    __shared__ unsigned long long As2[2][BK][BM];
    __shared__ float Bs[2][BK * BN];

    const int tid  = threadIdx.x;
    const int rb   = blockIdx.x * BM;

    const int arow = tid >> 2;        // 0..63 : A-tile row this thread loads
    const int aseg = tid & 3;         // 0..3  : 4-int segment within 16-wide k
    const int m0   = (tid >> 5) * 8;  // warp-uniform row group (A reads broadcast)
    const int c0   = (tid & 31) * 8;  // 8-column group

    unsigned long long acc[8][4];
#pragma unroll
    for (int r = 0; r < 8; r++)
#pragma unroll
        for (int c = 0; c < 4; c++) acc[r][c] = 0ull;

    int deg_i = 0;
    const int T = N_NODES / BK;   // 512 k-tiles

    const int4* arow_ptr =
        (const int4*)(adj + (size_t)(rb + arow) * N_NODES) + aseg;

    // ---- prefetch tile 0 ----
    int4   av = arow_ptr[0];
    float4 bv[4];
    {
        const float4* xs = (const float4*)x;
#pragma unroll
        for (int i = 0; i < 4; i++) bv[i] = xs[tid + i * NTHREADS];
    }
    // ---- store tile 0 into buffer 0 ----
#pragma unroll
    for (int j = 0; j < 4; j++) {
        const int vj = (&av.x)[j];
        const float f = (vj == 1) ? 1.0f : 0.0f;
        deg_i += (vj == 1);
        As2[0][aseg * 4 + j][arow] = pack2(f, f);
    }
    {
        float4* bdst = (float4*)Bs[0];
#pragma unroll
        for (int i = 0; i < 4; i++) bdst[tid + i * NTHREADS] = bv[i];
    }
    __syncthreads();

#pragma unroll 1
    for (int t = 0; t < T; t++) {
        const int buf = t & 1;
        if (t + 1 < T) {
            const int k0 = (t + 1) * BK;
            av = arow_ptr[k0 >> 2];
            const float4* xs = (const float4*)(x + (size_t)k0 * IN_F);
#pragma unroll
            for (int i = 0; i < 4; i++) bv[i] = xs[tid + i * NTHREADS];
        }

#pragma unroll
        for (int kk = 0; kk < BK; kk++) {
            ulonglong2 a01 = *(const ulonglong2*)&As2[buf][kk][m0];
            ulonglong2 a23 = *(const ulonglong2*)&As2[buf][kk][m0 + 2];
            ulonglong2 a45 = *(const ulonglong2*)&As2[buf][kk][m0 + 4];
            ulonglong2 a67 = *(const ulonglong2*)&As2[buf][kk][m0 + 6];
            const float* brow = &Bs[buf][kk * BN + c0];
            ulonglong2 b01 = *(const ulonglong2*)brow;
            ulonglong2 b23 = *(const ulonglong2*)(brow + 4);
            const unsigned long long a[8] = {a01.x, a01.y, a23.x, a23.y,
                                             a45.x, a45.y, a67.x, a67.y};
            const unsigned long long b[4] = {b01.x, b01.y, b23.x, b23.y};
#pragma unroll
            for (int r = 0; r < 8; r++)
#pragma unroll
                for (int c = 0; c < 4; c++)
                    acc[r][c] = ffma2(a[r], b[c], acc[r][c]);
        }

        if (t + 1 < T) {
            __syncthreads();
            const int nb = buf ^ 1;
#pragma unroll
            for (int j = 0; j < 4; j++) {
                const int vj = (&av.x)[j];
                const float f = (vj == 1) ? 1.0f : 0.0f;
                deg_i += (vj == 1);
                As2[nb][aseg * 4 + j][arow] = pack2(f, f);
            }
            float4* bdst = (float4*)Bs[nb];
#pragma unroll
            for (int i = 0; i < 4; i++) bdst[tid + i * NTHREADS] = bv[i];
            __syncthreads();
        }
    }

    // degree: reduce the 4 k-segments of each row within a quad of lanes
    deg_i += __shfl_xor_sync(0xffffffffu, deg_i, 1);
    deg_i += __shfl_xor_sync(0xffffffffu, deg_i, 2);
    __syncthreads();
    float* degS = (float*)&As2[0][0][0];  // reuse dead buffer 0
    if ((tid & 3) == 0) degS[arow] = (float)deg_i;
    __syncthreads();

    // epilogue: n_x[:, 0:256] = x1 / deg
#pragma unroll
    for (int r = 0; r < 8; r++) {
        const int row = m0 + r;
        const float inv = 1.0f / degS[row];
        const float2 p0 = unpack2(acc[r][0]);
        const float2 p1 = unpack2(acc[r][1]);
        const float2 p2 = unpack2(acc[r][2]);
        const float2 p3 = unpack2(acc[r][3]);
        float4 o0 = make_float4(p0.x * inv, p0.y * inv, p1.x * inv, p1.y * inv);
        float4 o1 = make_float4(p2.x * inv, p2.y * inv, p3.x * inv, p3.y * inv);
        float* dst = g_nx + (size_t)(rb + row) * TWO_F + c0;
        *(float4*)dst       = o0;
        *(float4*)(dst + 4) = o1;
    }

    // n_x[:, 256:512] = x
#pragma unroll 1
    for (int i = tid; i < BM * (IN_F / 4); i += NTHREADS) {
        const int row = i >> 6;        // 64 float4 per row
        const int cc  = i & 63;
        float4 v = ((const float4*)(x + (size_t)(rb + row) * IN_F))[cc];
        ((float4*)(g_nx + (size_t)(rb + row) * TWO_F + IN_F))[cc] = v;
    }
}

// =================== Stage 2: out[k] = n_x @ W[k] + bias ===================
__global__ __launch_bounds__(NTHREADS) void sage_out(const float* __restrict__ w,
                                                     const float* __restrict__ bias,
                                                     float* __restrict__ out)
{
    __shared__ unsigned long long As2[2][BK][BM];
    __shared__ float Bs[2][BK * BN];

    const int tid = threadIdx.x;
    const int rb  = blockIdx.x * BM;
    const int kz  = blockIdx.y;
    const float* wk = w + (size_t)kz * TWO_F * OUT_F;

    const int arow = tid >> 2;
    const int aseg = tid & 3;
    const int m0   = (tid >> 5) * 8;
    const int c0   = (tid & 31) * 8;

    unsigned long long acc[8][4];
#pragma unroll
    for (int r = 0; r < 8; r++)
#pragma unroll
        for (int c = 0; c < 4; c++) acc[r][c] = 0ull;

    const int T = TWO_F / BK;   // 32 k-tiles

    const float4* arow_ptr =
        (const float4*)(g_nx + (size_t)(rb + arow) * TWO_F) + aseg;

    float4 av = arow_ptr[0];
    float4 bv[4];
    {
        const float4* ws = (const float4*)wk;
#pragma unroll
        for (int i = 0; i < 4; i++) bv[i] = ws[tid + i * NTHREADS];
    }
#pragma unroll
    for (int j = 0; j < 4; j++) {
        const float f = (&av.x)[j];
        As2[0][aseg * 4 + j][arow] = pack2(f, f);
    }
    {
        float4* bdst = (float4*)Bs[0];
#pragma unroll
        for (int i = 0; i < 4; i++) bdst[tid + i * NTHREADS] = bv[i];
    }
    __syncthreads();

#pragma unroll 1
    for (int t = 0; t < T; t++) {
        const int buf = t & 1;
        if (t + 1 < T) {
            const int k0 = (t + 1) * BK;
            av = arow_ptr[k0 >> 2];
            const float4* ws = (const float4*)(wk + (size_t)k0 * OUT_F);
#pragma unroll
            for (int i = 0; i < 4; i++) bv[i] = ws[tid + i * NTHREADS];
        }

#pragma unroll
        for (int kk = 0; kk < BK; kk++) {
            ulonglong2 a01 = *(const ulonglong2*)&As2[buf][kk][m0];
            ulonglong2 a23 = *(const ulonglong2*)&As2[buf][kk][m0 + 2];
            ulonglong2 a45 = *(const ulonglong2*)&As2[buf][kk][m0 + 4];
            ulonglong2 a67 = *(const ulonglong2*)&As2[buf][kk][m0 + 6];
            const float* brow = &Bs[buf][kk * BN + c0];
            ulonglong2 b01 = *(const ulonglong2*)brow;
            ulonglong2 b23 = *(const ulonglong2*)(brow + 4);
            const unsigned long long a[8] = {a01.x, a01.y, a23.x, a23.y,
                                             a45.x, a45.y, a67.x, a67.y};
            const unsigned long long b[4] = {b01.x, b01.y, b23.x, b23.y};
#pragma unroll
            for (int r = 0; r < 8; r++)
#pragma unroll
                for (int c = 0; c < 4; c++)
                    acc[r][c] = ffma2(a[r], b[c], acc[r][c]);
        }

        if (t + 1 < T) {
            __syncthreads();
            const int nb = buf ^ 1;
#pragma unroll
            for (int j = 0; j < 4; j++) {
                const float f = (&av.x)[j];
                As2[nb][aseg * 4 + j][arow] = pack2(f, f);
            }
            float4* bdst = (float4*)Bs[nb];
#pragma unroll
            for (int i = 0; i < 4; i++) bdst[tid + i * NTHREADS] = bv[i];
            __syncthreads();
        }
    }

    const float4 bz0 = *(const float4*)(bias + c0);
    const float4 bz1 = *(const float4*)(bias + c0 + 4);
    float* outk = out + (size_t)kz * N_NODES * OUT_F;

#pragma unroll
    for (int r = 0; r < 8; r++) {
        const int row = m0 + r;
        const float2 p0 = unpack2(acc[r][0]);
        const float2 p1 = unpack2(acc[r][1]);
        const float2 p2 = unpack2(acc[r][2]);
        const float2 p3 = unpack2(acc[r][3]);
        float4 o0 = make_float4(p0.x + bz0.x, p0.y + bz0.y,
                                p1.x + bz0.z, p1.y + bz0.w);
        float4 o1 = make_float4(p2.x + bz1.x, p2.y + bz1.y,
                                p3.x + bz1.z, p3.y + bz1.w);
        float* dst = outk + (size_t)(rb + row) * OUT_F + c0;
        *(float4*)dst       = o0;
        *(float4*)(dst + 4) = o1;
    }
}

extern "C" void kernel_launch(void* const* d_in, const int* in_sizes, int n_in,
                              void* d_out, int out_size)
{
    // identify inputs by element count (robust to whether scalar g is passed)
    const float* x    = nullptr;
    const int*   adj  = nullptr;
    const float* w    = nullptr;
    const float* bias = nullptr;
    for (int i = 0; i < n_in; i++) {
        switch (in_sizes[i]) {
            case N_NODES * IN_F:      x    = (const float*)d_in[i]; break;
            case N_NODES * N_NODES:   adj  = (const int*)d_in[i];   break;
            case 3 * TWO_F * OUT_F:   w    = (const float*)d_in[i]; break;
            case OUT_F:               bias = (const float*)d_in[i]; break;
            default: break; // scalar g, unused
        }
    }

    sage_agg<<<dim3(N_NODES / BM), NTHREADS>>>(adj, x);
    sage_out<<<dim3(N_NODES / BM, 3), NTHREADS>>>(w, bias, (float*)d_out);
}

// round 4
// speedup vs baseline: 3.1658x; 3.1658x over previous
#include <cuda_runtime.h>
#include <cuda_bf16.h>
#include <cstdint>

// CoreSageLayer via baseline-PTX tensor path (mma.sync bf16, sm_103-safe):
//   out[k] = concat((adj@x)/deg, x) @ W[k] + bias
// prep_split : x -> xT hi/lo bf16 (stage-1 B operand, [F][N] k-major)
// prep_w     : W -> W^T hi/lo bf16 ([3][O][2F] k-major, stage-2 B operand)
// sage_agg   : HMMA GEMM partials  part[z] = adj[:, zK:...] @ x_hi + @ x_lo
//              (fp32 acc, fused partial degree), K-split z=0,1
// sage_combine: n_x = [ (p0+p1)/deg | x ] emitted as bf16 hi/lo (A operand)
// sage_out   : HMMA GEMM out[k] = Ah Wh + Ah Wl + Al Wh + bias (fp32)

#define N_NODES 8192
#define IN_F    256
#define TWO_F   512
#define OUT_F   256
#define ROWB    144          // padded smem row: 64 bf16 + 8 pad = 144 bytes

// ---------------- static device scratch ----------------
__device__ __nv_bfloat16 g_xT_hi[(size_t)IN_F * N_NODES];
__device__ __nv_bfloat16 g_xT_lo[(size_t)IN_F * N_NODES];
__device__ __nv_bfloat16 g_nxh[(size_t)N_NODES * TWO_F];
__device__ __nv_bfloat16 g_nxl[(size_t)N_NODES * TWO_F];
__device__ __nv_bfloat16 g_wTh[3u * OUT_F * TWO_F];
__device__ __nv_bfloat16 g_wTl[3u * OUT_F * TWO_F];
__device__ float g_part[2ull * N_NODES * IN_F];
__device__ float g_degp[2 * N_NODES];

// ---------------- PTX helpers (all baseline, no sm_103a features) --------
__device__ __forceinline__ uint32_t smem_u32(const void* p) {
    uint32_t a;
    asm("{ .reg .u64 t; cvta.to.shared.u64 t, %1; cvt.u32.u64 %0, t; }"
        : "=r"(a) : "l"(p));
    return a;
}
#define LDMX4(r, addr) \
    asm volatile("ldmatrix.sync.aligned.m8n8.x4.shared.b16 {%0,%1,%2,%3}, [%4];" \
        : "=r"((r)[0]), "=r"((r)[1]), "=r"((r)[2]), "=r"((r)[3]) : "r"(addr))
#define MMA(d, a, b0, b1) \
    asm volatile("mma.sync.aligned.m16n8k16.row.col.f32.bf16.bf16.f32 " \
        "{%0,%1,%2,%3}, {%4,%5,%6,%7}, {%8,%9}, {%0,%1,%2,%3};" \
        : "+f"((d)[0]), "+f"((d)[1]), "+f"((d)[2]), "+f"((d)[3]) \
        : "r"((a)[0]), "r"((a)[1]), "r"((a)[2]), "r"((a)[3]), "r"(b0), "r"(b1))
#define CP16(dst, src) \
    asm volatile("cp.async.cg.shared.global [%0], [%1], 16;" \
        :: "r"(dst), "l"(src) : "memory")
#define CPCOMMIT()  asm volatile("cp.async.commit_group;" ::: "memory")
#define CPWAITALL() asm volatile("cp.async.wait_group 0;" ::: "memory")
#define STS128U(addr, v) \
    asm volatile("st.shared.v4.b32 [%0], {%1,%2,%3,%4};" \
        :: "r"(addr), "r"((v).x), "r"((v).y), "r"((v).z), "r"((v).w) : "memory")

__device__ __forceinline__ uint32_t pkbf2(float a, float b) {
    __nv_bfloat162 t = __floats2bfloat162_rn(a, b);
    return *reinterpret_cast<uint32_t*>(&t);
}

// =================== prep: x -> xT hi/lo ===================
__global__ void prep_split(const float* __restrict__ x) {
    __shared__ float t[32][33];
    const int tx = threadIdx.x, ty = threadIdx.y;
    const int k0 = blockIdx.x * 32, n0 = blockIdx.y * 32;
#pragma unroll
    for (int i = 0; i < 32; i += 8)
        t[ty + i][tx] = x[(size_t)(k0 + ty + i) * IN_F + n0 + tx];
    __syncthreads();
#pragma unroll
    for (int i = 0; i < 32; i += 8) {
        const float v = t[tx][ty + i];
        const __nv_bfloat16 h = __float2bfloat16(v);
        const float lo = v - __bfloat162float(h);
        const size_t o = (size_t)(n0 + ty + i) * N_NODES + k0 + tx;
        g_xT_hi[o] = h;
        g_xT_lo[o] = __float2bfloat16(lo);
    }
}

// =================== prep: W -> W^T hi/lo ===================
__global__ void prep_w(const float* __restrict__ w) {
    __shared__ float t[32][33];
    const int tx = threadIdx.x, ty = threadIdx.y;
    const int f0 = blockIdx.x * 32, o0 = blockIdx.y * 32, h = blockIdx.z;
    const float* wk = w + (size_t)h * TWO_F * OUT_F;
#pragma unroll
    for (int i = 0; i < 32; i += 8)
        t[ty + i][tx] = wk[(size_t)(f0 + ty + i) * OUT_F + o0 + tx];
    __syncthreads();
#pragma unroll
    for (int i = 0; i < 32; i += 8) {
        const float v = t[tx][ty + i];                 // W[f0+tx][o0+ty+i]
        const __nv_bfloat16 hi = __float2bfloat16(v);
        const float lo = v - __bfloat162float(hi);
        const size_t o = ((size_t)h * OUT_F + o0 + ty + i) * TWO_F + f0 + tx;
        g_wTh[o] = hi;
        g_wTl[o] = __float2bfloat16(lo);
    }
}

// =================== Stage 1: adj aggregate (HMMA) ===================
// CTA tile 128m x 256n, BK=64, K-split z in {0,1}. 512 threads = 16 warps
// (4x4), warp tile 32m x 64n. smem rows padded to 144B.
#define S1_A0   0u
#define S1_A1   18432u
#define S1_BH0  36864u
#define S1_BH1  73728u
#define S1_BL0  110592u
#define S1_BL1  147456u
#define S1_SMEM 184320

__global__ __launch_bounds__(512, 1)
void sage_agg(const int* __restrict__ adj)
{
    extern __shared__ char smem[];
    const uint32_t sb = smem_u32(smem);
    const int tid = threadIdx.x, lane = tid & 31, wid = tid >> 5;
    const int wy = wid & 3, wx = wid >> 2;
    const int rb  = blockIdx.x * 128;
    const int z   = blockIdx.y;
    const int kzb = z * (N_NODES / 2);
    const int T   = (N_NODES / 2) / 64;   // 64 chunks

    const int arow = tid >> 2, aseg = tid & 3;
    const int brow = tid >> 1, bhalf = tid & 1;

    const int* aptr = adj + (size_t)(rb + arow) * N_NODES + kzb + aseg * 16;
    const __nv_bfloat16* bh = g_xT_hi + (size_t)brow * N_NODES + kzb + bhalf * 32;
    const __nv_bfloat16* bl = g_xT_lo + (size_t)brow * N_NODES + kzb + bhalf * 32;

    const uint32_t a_sts = (uint32_t)(arow * ROWB + aseg * 32);
    const uint32_t b_sts = (uint32_t)(brow * ROWB + bhalf * 64);
    const uint32_t aoff[2]  = {S1_A0, S1_A1};
    const uint32_t bhoff[2] = {S1_BH0, S1_BH1};
    const uint32_t bloff[2] = {S1_BL0, S1_BL1};

    const uint32_t a_ld = (uint32_t)((wy * 32 + (lane & 15)) * ROWB) + (lane & 16);
    const uint32_t b_ld = (uint32_t)((wx * 64 + (lane & 15)) * ROWB) + (lane & 16);

    float acc[2][8][4];
#pragma unroll
    for (int i = 0; i < 2; i++)
#pragma unroll
        for (int j = 0; j < 8; j++)
#pragma unroll
            for (int k = 0; k < 4; k++) acc[i][j][k] = 0.0f;

    int deg = 0;

    // ---- preload chunk 0 into buffer 0
    {
#pragma unroll
        for (int j = 0; j < 4; j++)
            CP16(sb + S1_BH0 + b_sts + j * 16, (const char*)bh + j * 16);
#pragma unroll
        for (int j = 0; j < 4; j++)
            CP16(sb + S1_BL0 + b_sts + j * 16, (const char*)bl + j * 16);
        CPCOMMIT();
        const int4* p = (const int4*)aptr;
        int4 v0 = p[0], v1 = p[1], v2 = p[2], v3 = p[3];
        deg += v0.x + v0.y + v0.z + v0.w + v1.x + v1.y + v1.z + v1.w +
               v2.x + v2.y + v2.z + v2.w + v3.x + v3.y + v3.z + v3.w;
        uint4 o1, o2;
        o1.x = (uint32_t)v0.x * 0x3F80u + (uint32_t)v0.y * 0x3F800000u;
        o1.y = (uint32_t)v0.z * 0x3F80u + (uint32_t)v0.w * 0x3F800000u;
        o1.z = (uint32_t)v1.x * 0x3F80u + (uint32_t)v1.y * 0x3F800000u;
        o1.w = (uint32_t)v1.z * 0x3F80u + (uint32_t)v1.w * 0x3F800000u;
        o2.x = (uint32_t)v2.x * 0x3F80u + (uint32_t)v2.y * 0x3F800000u;
        o2.y = (uint32_t)v2.z * 0x3F80u + (uint32_t)v2.w * 0x3F800000u;
        o2.z = (uint32_t)v3.x * 0x3F80u + (uint32_t)v3.y * 0x3F800000u;
        o2.w = (uint32_t)v3.z * 0x3F80u + (uint32_t)v3.w * 0x3F800000u;
        STS128U(sb + S1_A0 + a_sts, o1);
        STS128U(sb + S1_A0 + a_sts + 16, o2);
        CPWAITALL();
    }
    __syncthreads();

#pragma unroll 1
    for (int c = 0; c < T; c++) {
        const int buf = c & 1;
        if (c + 1 < T) {
            const size_t ko = (size_t)(c + 1) * 64;
            const char* bhs = (const char*)(bh + ko);
            const char* bls = (const char*)(bl + ko);
            const uint32_t bhD = sb + bhoff[buf ^ 1] + b_sts;
            const uint32_t blD = sb + bloff[buf ^ 1] + b_sts;
#pragma unroll
            for (int j = 0; j < 4; j++) CP16(bhD + j * 16, bhs + j * 16);
#pragma unroll
            for (int j = 0; j < 4; j++) CP16(blD + j * 16, bls + j * 16);
            CPCOMMIT();
            const int4* p = (const int4*)(aptr + ko);
            int4 v0 = p[0], v1 = p[1], v2 = p[2], v3 = p[3];
            deg += v0.x + v0.y + v0.z + v0.w + v1.x + v1.y + v1.z + v1.w +
                   v2.x + v2.y + v2.z + v2.w + v3.x + v3.y + v3.z + v3.w;
            uint4 o1, o2;
            o1.x = (uint32_t)v0.x * 0x3F80u + (uint32_t)v0.y * 0x3F800000u;
            o1.y = (uint32_t)v0.z * 0x3F80u + (uint32_t)v0.w * 0x3F800000u;
            o1.z = (uint32_t)v1.x * 0x3F80u + (uint32_t)v1.y * 0x3F800000u;
            o1.w = (uint32_t)v1.z * 0x3F80u + (uint32_t)v1.w * 0x3F800000u;
            o2.x = (uint32_t)v2.x * 0x3F80u + (uint32_t)v2.y * 0x3F800000u;
            o2.y = (uint32_t)v2.z * 0x3F80u + (uint32_t)v2.w * 0x3F800000u;
            o2.z = (uint32_t)v3.x * 0x3F80u + (uint32_t)v3.y * 0x3F800000u;
            o2.w = (uint32_t)v3.z * 0x3F80u + (uint32_t)v3.w * 0x3F800000u;
            const uint32_t aD = sb + aoff[buf ^ 1] + a_sts;
            STS128U(aD, o1);
            STS128U(aD + 16, o2);
        }

        const uint32_t ab = sb + aoff[buf];
        const uint32_t hb = sb + bhoff[buf];
        const uint32_t lb = sb + bloff[buf];
#pragma unroll
        for (int ks = 0; ks < 4; ks++) {
            uint32_t A0[4], A1[4], B[16];
            LDMX4(A0, ab + a_ld + ks * 32);
            LDMX4(A1, ab + a_ld + 16 * ROWB + ks * 32);
            LDMX4(&B[0],  hb + b_ld + ks * 32);
            LDMX4(&B[4],  hb + b_ld + 16 * ROWB + ks * 32);
            LDMX4(&B[8],  hb + b_ld + 32 * ROWB + ks * 32);
            LDMX4(&B[12], hb + b_ld + 48 * ROWB + ks * 32);
#pragma unroll
            for (int t = 0; t < 4; t++) {
                MMA(acc[0][2 * t],     A0, B[4 * t + 0], B[4 * t + 2]);
                MMA(acc[0][2 * t + 1], A0, B[4 * t + 1], B[4 * t + 3]);
                MMA(acc[1][2 * t],     A1, B[4 * t + 0], B[4 * t + 2]);
                MMA(acc[1][2 * t + 1], A1, B[4 * t + 1], B[4 * t + 3]);
            }
            LDMX4(&B[0],  lb + b_ld + ks * 32);
            LDMX4(&B[4],  lb + b_ld + 16 * ROWB + ks * 32);
            LDMX4(&B[8],  lb + b_ld + 32 * ROWB + ks * 32);
            LDMX4(&B[12], lb + b_ld + 48 * ROWB + ks * 32);
#pragma unroll
            for (int t = 0; t < 4; t++) {
                MMA(acc[0][2 * t],     A0, B[4 * t + 0], B[4 * t + 2]);
                MMA(acc[0][2 * t + 1], A0, B[4 * t + 1], B[4 * t + 3]);
                MMA(acc[1][2 * t],     A1, B[4 * t + 0], B[4 * t + 2]);
                MMA(acc[1][2 * t + 1], A1, B[4 * t + 1], B[4 * t + 3]);
            }
        }
        if (c + 1 < T) CPWAITALL();
        __syncthreads();
    }

    // partial degree
    deg += __shfl_xor_sync(0xffffffffu, deg, 1);
    deg += __shfl_xor_sync(0xffffffffu, deg, 2);
    if ((tid & 3) == 0)
        g_degp[z * N_NODES + rb + arow] = (float)deg;

    // partial sums
    float* pb = g_part + ((size_t)z * N_NODES + rb) * IN_F;
#pragma unroll
    for (int mi = 0; mi < 2; mi++)
#pragma unroll
        for (int nt = 0; nt < 8; nt++) {
            const int r0 = wy * 32 + mi * 16 + (lane >> 2);
            const int cc = wx * 64 + nt * 8 + (lane & 3) * 2;
            *(float2*)(pb + (size_t)r0 * IN_F + cc) =
                make_float2(acc[mi][nt][0], acc[mi][nt][1]);
            *(float2*)(pb + (size_t)(r0 + 8) * IN_F + cc) =
                make_float2(acc[mi][nt][2], acc[mi][nt][3]);
        }
}

// =================== combine: n_x as bf16 hi/lo ===================
__global__ void sage_combine(const float* __restrict__ x) {
    const int id = blockIdx.x * 256 + threadIdx.x;   // 0 .. 8192*128
    const int row = id >> 7;
    const int s   = id & 127;
    float4 v;
    int col;
    if (s < 64) {
        col = s * 4;
        const float4 p0 = *(const float4*)(g_part + (size_t)row * IN_F + col);
        const float4 p1 =
            *(const float4*)(g_part + (size_t)(N_NODES + row) * IN_F + col);
        const float inv = 1.0f / (g_degp[row] + g_degp[N_NODES + row]);
        v = make_float4((p0.x + p1.x) * inv, (p0.y + p1.y) * inv,
                        (p0.z + p1.z) * inv, (p0.w + p1.w) * inv);
    } else {
        col = IN_F + (s - 64) * 4;
        v = *(const float4*)(x + (size_t)row * IN_F + (s - 64) * 4);
    }
    const float hx = __bfloat162float(__float2bfloat16(v.x));
    const float hy = __bfloat162float(__float2bfloat16(v.y));
    const float hz = __bfloat162float(__float2bfloat16(v.z));
    const float hw = __bfloat162float(__float2bfloat16(v.w));
    uint2 H, L;
    H.x = pkbf2(v.x, v.y);
    H.y = pkbf2(v.z, v.w);
    L.x = pkbf2(v.x - hx, v.y - hy);
    L.y = pkbf2(v.z - hz, v.w - hw);
    *(uint2*)(g_nxh + (size_t)row * TWO_F + col) = H;
    *(uint2*)(g_nxl + (size_t)row * TWO_F + col) = L;
}

// =================== Stage 2: out[k] = n_x @ W[k] + bias ===================
#define S2_AH0  0u
#define S2_AH1  18432u
#define S2_AL0  36864u
#define S2_AL1  55296u
#define S2_BH0  73728u
#define S2_BH1  110592u
#define S2_BL0  147456u
#define S2_BL1  184320u
#define S2_SMEM 221184

__global__ __launch_bounds__(512, 1)
void sage_out(const float* __restrict__ bias, float* __restrict__ out)
{
    extern __shared__ char smem[];
    const uint32_t sb = smem_u32(smem);
    const int tid = threadIdx.x, lane = tid & 31, wid = tid >> 5;
    const int wy = wid & 3, wx = wid >> 2;
    const int rb = blockIdx.x * 128;
    const int hd = blockIdx.y;
    const int T  = TWO_F / 64;   // 8

    const int arow = tid >> 2, aseg = tid & 3;
    const int brow = tid >> 1, bhalf = tid & 1;

    const __nv_bfloat16* ah = g_nxh + (size_t)(rb + arow) * TWO_F + aseg * 16;
    const __nv_bfloat16* al = g_nxl + (size_t)(rb + arow) * TWO_F + aseg * 16;
    const __nv_bfloat16* wh = g_wTh + ((size_t)hd * OUT_F + brow) * TWO_F + bhalf * 32;
    const __nv_bfloat16* wl = g_wTl + ((size_t)hd * OUT_F + brow) * TWO_F + bhalf * 32;

    const uint32_t a_sts = (uint32_t)(arow * ROWB + aseg * 32);
    const uint32_t b_sts = (uint32_t)(brow * ROWB + bhalf * 64);
    const uint32_t ahoff[2] = {S2_AH0, S2_AH1};
    const uint32_t aloff[2] = {S2_AL0, S2_AL1};
    const uint32_t bhoff[2] = {S2_BH0, S2_BH1};
    const uint32_t bloff[2] = {S2_BL0, S2_BL1};

    const uint32_t a_ld = (uint32_t)((wy * 32 + (lane & 15)) * ROWB) + (lane & 16);
    const uint32_t b_ld = (uint32_t)((wx * 64 + (lane & 15)) * ROWB) + (lane & 16);

    float acc[2][8][4];
#pragma unroll
    for (int i = 0; i < 2; i++)
#pragma unroll
        for (int j = 0; j < 8; j++)
#pragma unroll
            for (int k = 0; k < 4; k++) acc[i][j][k] = 0.0f;

    // preload chunk 0
    {
#pragma unroll
        for (int j = 0; j < 2; j++) {
            CP16(sb + S2_AH0 + a_sts + j * 16, (const char*)ah + j * 16);
            CP16(sb + S2_AL0 + a_sts + j * 16, (const char*)al + j * 16);
        }
#pragma unroll
        for (int j = 0; j < 4; j++) {
            CP16(sb + S2_BH0 + b_sts + j * 16, (const char*)wh + j * 16);
            CP16(sb + S2_BL0 + b_sts + j * 16, (const char*)wl + j * 16);
        }
        CPCOMMIT();
        CPWAITALL();
    }
    __syncthreads();

#pragma unroll 1
    for (int c = 0; c < T; c++) {
        const int buf = c & 1;
        if (c + 1 < T) {
            const size_t ko = (size_t)(c + 1) * 64;
            const uint32_t nb = buf ^ 1;
#pragma unroll
            for (int j = 0; j < 2; j++) {
                CP16(sb + ahoff[nb] + a_sts + j * 16, (const char*)(ah + ko) + j * 16);
                CP16(sb + aloff[nb] + a_sts + j * 16, (const char*)(al + ko) + j * 16);
            }
#pragma unroll
            for (int j = 0; j < 4; j++) {
                CP16(sb + bhoff[nb] + b_sts + j * 16, (const char*)(wh + ko) + j * 16);
                CP16(sb + bloff[nb] + b_sts + j * 16, (const char*)(wl + ko) + j * 16);
            }
            CPCOMMIT();
        }

        const uint32_t ahb = sb + ahoff[buf];
        const uint32_t alb = sb + aloff[buf];
        const uint32_t bhb = sb + bhoff[buf];
        const uint32_t blb = sb + bloff[buf];
#pragma unroll
        for (int ks = 0; ks < 4; ks++) {
            uint32_t AH0[4], AH1[4], AL0[4], AL1[4], B[16];
            LDMX4(AH0, ahb + a_ld + ks * 32);
            LDMX4(AH1, ahb + a_ld + 16 * ROWB + ks * 32);
            LDMX4(AL0, alb + a_ld + ks * 32);
            LDMX4(AL1, alb + a_ld + 16 * ROWB + ks * 32);
            LDMX4(&B[0],  bhb + b_ld + ks * 32);
            LDMX4(&B[4],  bhb + b_ld + 16 * ROWB + ks * 32);
            LDMX4(&B[8],  bhb + b_ld + 32 * ROWB + ks * 32);
            LDMX4(&B[12], bhb + b_ld + 48 * ROWB + ks * 32);
#pragma unroll
            for (int t = 0; t < 4; t++) {
                MMA(acc[0][2 * t],     AH0, B[4 * t + 0], B[4 * t + 2]);
                MMA(acc[0][2 * t + 1], AH0, B[4 * t + 1], B[4 * t + 3]);
                MMA(acc[1][2 * t],     AH1, B[4 * t + 0], B[4 * t + 2]);
                MMA(acc[1][2 * t + 1], AH1, B[4 * t + 1], B[4 * t + 3]);
                MMA(acc[0][2 * t],     AL0, B[4 * t + 0], B[4 * t + 2]);
                MMA(acc[0][2 * t + 1], AL0, B[4 * t + 1], B[4 * t + 3]);
                MMA(acc[1][2 * t],     AL1, B[4 * t + 0], B[4 * t + 2]);
                MMA(acc[1][2 * t + 1], AL1, B[4 * t + 1], B[4 * t + 3]);
            }
            LDMX4(&B[0],  blb + b_ld + ks * 32);
            LDMX4(&B[4],  blb + b_ld + 16 * ROWB + ks * 32);
            LDMX4(&B[8],  blb + b_ld + 32 * ROWB + ks * 32);
            LDMX4(&B[12], blb + b_ld + 48 * ROWB + ks * 32);
#pragma unroll
            for (int t = 0; t < 4; t++) {
                MMA(acc[0][2 * t],     AH0, B[4 * t + 0], B[4 * t + 2]);
                MMA(acc[0][2 * t + 1], AH0, B[4 * t + 1], B[4 * t + 3]);
                MMA(acc[1][2 * t],     AH1, B[4 * t + 0], B[4 * t + 2]);
                MMA(acc[1][2 * t + 1], AH1, B[4 * t + 1], B[4 * t + 3]);
            }
        }
        if (c + 1 < T) CPWAITALL();
        __syncthreads();
    }

    float* ob = out + ((size_t)hd * N_NODES + rb) * OUT_F;
#pragma unroll
    for (int mi = 0; mi < 2; mi++)
#pragma unroll
        for (int nt = 0; nt < 8; nt++) {
            const int r0 = wy * 32 + mi * 16 + (lane >> 2);
            const int cc = wx * 64 + nt * 8 + (lane & 3) * 2;
            const float2 bz = *(const float2*)(bias + cc);
            *(float2*)(ob + (size_t)r0 * OUT_F + cc) =
                make_float2(acc[mi][nt][0] + bz.x, acc[mi][nt][1] + bz.y);
            *(float2*)(ob + (size_t)(r0 + 8) * OUT_F + cc) =
                make_float2(acc[mi][nt][2] + bz.x, acc[mi][nt][3] + bz.y);
        }
}

// =================== host launch ===================
extern "C" void kernel_launch(void* const* d_in, const int* in_sizes, int n_in,
                              void* d_out, int out_size)
{
    const float* x    = nullptr;
    const int*   adj  = nullptr;
    const float* w    = nullptr;
    const float* bias = nullptr;
    for (int i = 0; i < n_in; i++) {
        switch (in_sizes[i]) {
            case N_NODES * IN_F:      x    = (const float*)d_in[i]; break;
            case N_NODES * N_NODES:   adj  = (const int*)d_in[i];   break;
            case 3 * TWO_F * OUT_F:   w    = (const float*)d_in[i]; break;
            case OUT_F:               bias = (const float*)d_in[i]; break;
            default: break;  // scalar g
        }
    }

    cudaFuncSetAttribute(sage_agg,
                         cudaFuncAttributeMaxDynamicSharedMemorySize, S1_SMEM);
    cudaFuncSetAttribute(sage_out,
                         cudaFuncAttributeMaxDynamicSharedMemorySize, S2_SMEM);

    prep_split<<<dim3(N_NODES / 32, IN_F / 32), dim3(32, 8)>>>(x);
    prep_w<<<dim3(TWO_F / 32, OUT_F / 32, 3), dim3(32, 8)>>>(w);
    sage_agg<<<dim3(N_NODES / 128, 2), 512, S1_SMEM>>>(adj);
    sage_combine<<<(N_NODES * 128) / 256, 256>>>(x);
    sage_out<<<dim3(N_NODES / 128, 3), 512, S2_SMEM>>>(bias, (float*)d_out);
}

// round 7
// speedup vs baseline: 5.6419x; 1.7821x over previous
#include <cuda_runtime.h>
#include <cuda_fp16.h>
#include <cstdint>

// CoreSageLayer, fp16 single-chain HMMA (sm_103-base PTX):
//   out[k] = concat((adj@x)/deg, x) @ W[k] + bias
// prep_split : x -> xT fp16 ([F][N] k-major, stage-1 B operand)
// prep_w     : W -> W^T fp16 ([3][O][2F] k-major, stage-2 B operand)
// sage_agg   : HMMA fp16 GEMM  part[z] = adj[:, zK:] @ xT, fp32 acc,
//              fused partial degree, K-split z in {0,1}
// sage_combine: n_x = [ (p0+p1)/deg | x ] emitted fp16 (stage-2 A operand)
// sage_out   : HMMA fp16 GEMM out[k] = n_x @ W[k]^T + bias (fp32 acc)

#define N_NODES 8192
#define IN_F    256
#define TWO_F   512
#define OUT_F   256
#define ROWB    144          // padded smem row: 64 fp16 + 8 pad = 144 bytes

// ---------------- static device scratch ----------------
__device__ __half g_xT[(size_t)IN_F * N_NODES];          // 4 MB
__device__ __half g_nx[(size_t)N_NODES * TWO_F];         // 8 MB
__device__ __half g_wT[3u * OUT_F * TWO_F];              // 768 KB
__device__ float  g_part[2ull * N_NODES * IN_F];         // 16 MB
__device__ float  g_degp[2 * N_NODES];

// ---------------- PTX helpers (baseline, sm_103-safe) --------
__device__ __forceinline__ uint32_t smem_u32(const void* p) {
    uint32_t a;
    asm("{ .reg .u64 t; cvta.to.shared.u64 t, %1; cvt.u32.u64 %0, t; }"
        : "=r"(a) : "l"(p));
    return a;
}
#define LDMX4(r, addr) \
    asm volatile("ldmatrix.sync.aligned.m8n8.x4.shared.b16 {%0,%1,%2,%3}, [%4];" \
        : "=r"((r)[0]), "=r"((r)[1]), "=r"((r)[2]), "=r"((r)[3]) : "r"(addr))
#define MMA(d, a, b0, b1) \
    asm volatile("mma.sync.aligned.m16n8k16.row.col.f32.f16.f16.f32 " \
        "{%0,%1,%2,%3}, {%4,%5,%6,%7}, {%8,%9}, {%0,%1,%2,%3};" \
        : "+f"((d)[0]), "+f"((d)[1]), "+f"((d)[2]), "+f"((d)[3]) \
        : "r"((a)[0]), "r"((a)[1]), "r"((a)[2]), "r"((a)[3]), "r"(b0), "r"(b1))
#define CP16(dst, src) \
    asm volatile("cp.async.cg.shared.global [%0], [%1], 16;" \
        :: "r"(dst), "l"(src) : "memory")
#define CPCOMMIT()  asm volatile("cp.async.commit_group;" ::: "memory")
#define CPWAITALL() asm volatile("cp.async.wait_group 0;" ::: "memory")
#define STS128U(addr, v) \
    asm volatile("st.shared.v4.b32 [%0], {%1,%2,%3,%4};" \
        :: "r"(addr), "r"((v).x), "r"((v).y), "r"((v).z), "r"((v).w) : "memory")

// =================== prep: x -> xT fp16 ===================
__global__ void prep_split(const float* __restrict__ x) {
    __shared__ float t[32][33];
    const int tx = threadIdx.x, ty = threadIdx.y;
    const int k0 = blockIdx.x * 32, n0 = blockIdx.y * 32;
#pragma unroll
    for (int i = 0; i < 32; i += 8)
        t[ty + i][tx] = x[(size_t)(k0 + ty + i) * IN_F + n0 + tx];
    __syncthreads();
#pragma unroll
    for (int i = 0; i < 32; i += 8)
        g_xT[(size_t)(n0 + ty + i) * N_NODES + k0 + tx] =
            __float2half_rn(t[tx][ty + i]);
}

// =================== prep: W -> W^T fp16 ===================
__global__ void prep_w(const float* __restrict__ w) {
    __shared__ float t[32][33];
    const int tx = threadIdx.x, ty = threadIdx.y;
    const int f0 = blockIdx.x * 32, o0 = blockIdx.y * 32, h = blockIdx.z;
    const float* wk = w + (size_t)h * TWO_F * OUT_F;
#pragma unroll
    for (int i = 0; i < 32; i += 8)
        t[ty + i][tx] = wk[(size_t)(f0 + ty + i) * OUT_F + o0 + tx];
    __syncthreads();
#pragma unroll
    for (int i = 0; i < 32; i += 8)
        g_wT[((size_t)h * OUT_F + o0 + ty + i) * TWO_F + f0 + tx] =
            __float2half_rn(t[tx][ty + i]);
}

// =================== Stage 1: adj aggregate (fp16 HMMA) ===================
// CTA tile 128m x 256n, BK=64, K-split z in {0,1}. 512 threads = 16 warps
// (4 m-rows x 4 n-cols), warp tile 32m x 64n. Padded 144B smem rows.
#define S1_A0   0u
#define S1_A1   18432u
#define S1_B0   36864u
#define S1_B1   73728u
#define S1_SMEM 110592

__global__ __launch_bounds__(512, 1)
void sage_agg(const int* __restrict__ adj)
{
    extern __shared__ char smem[];
    const uint32_t sb = smem_u32(smem);
    const int tid = threadIdx.x, lane = tid & 31, wid = tid >> 5;
    const int wy = wid & 3, wx = wid >> 2;
    const int rb  = blockIdx.x * 128;
    const int z   = blockIdx.y;
    const int kzb = z * (N_NODES / 2);
    const int T   = (N_NODES / 2) / 64;   // 64 chunks

    const int arow = tid >> 2, aseg = tid & 3;   // 4 threads per A row (64 ints)
    const int brow = tid >> 1, bhalf = tid & 1;  // 2 threads per B row (128 B)

    const int*    aptr = adj + (size_t)(rb + arow) * N_NODES + kzb + aseg * 16;
    const __half* bsrc = g_xT + (size_t)brow * N_NODES + kzb + bhalf * 32;

    const uint32_t a_sts = (uint32_t)(arow * ROWB + aseg * 32);
    const uint32_t b_sts = (uint32_t)(brow * ROWB + bhalf * 64);
    const uint32_t aoff[2] = {S1_A0, S1_A1};
    const uint32_t boff[2] = {S1_B0, S1_B1};

    const uint32_t a_ld = (uint32_t)((wy * 32 + (lane & 15)) * ROWB) + (lane & 16);
    const uint32_t b_ld = (uint32_t)((wx * 64 + (lane & 15)) * ROWB) + (lane & 16);

    float acc[2][8][4];
#pragma unroll
    for (int i = 0; i < 2; i++)
#pragma unroll
        for (int j = 0; j < 8; j++)
#pragma unroll
            for (int k = 0; k < 4; k++) acc[i][j][k] = 0.0f;

    int deg = 0;

    // fp16 1.0 = 0x3C00; pack two lanes per u32
    auto cvt_sts = [&](const int4* v, uint32_t dstA) {
        uint4 o1, o2;
        o1.x = (uint32_t)v[0].x * 0x3C00u + (uint32_t)v[0].y * 0x3C000000u;
        o1.y = (uint32_t)v[0].z * 0x3C00u + (uint32_t)v[0].w * 0x3C000000u;
        o1.z = (uint32_t)v[1].x * 0x3C00u + (uint32_t)v[1].y * 0x3C000000u;
        o1.w = (uint32_t)v[1].z * 0x3C00u + (uint32_t)v[1].w * 0x3C000000u;
        o2.x = (uint32_t)v[2].x * 0x3C00u + (uint32_t)v[2].y * 0x3C000000u;
        o2.y = (uint32_t)v[2].z * 0x3C00u + (uint32_t)v[2].w * 0x3C000000u;
        o2.z = (uint32_t)v[3].x * 0x3C00u + (uint32_t)v[3].y * 0x3C000000u;
        o2.w = (uint32_t)v[3].z * 0x3C00u + (uint32_t)v[3].w * 0x3C000000u;
        STS128U(dstA, o1);
        STS128U(dstA + 16, o2);
    };

    // ---- preload chunk 0 into buffer 0
    {
#pragma unroll
        for (int j = 0; j < 4; j++)
            CP16(sb + S1_B0 + b_sts + j * 16, (const char*)bsrc + j * 16);
        CPCOMMIT();
        int4 v[4];
        const int4* p = (const int4*)aptr;
#pragma unroll
        for (int j = 0; j < 4; j++) v[j] = p[j];
#pragma unroll
        for (int j = 0; j < 4; j++)
            deg += v[j].x + v[j].y + v[j].z + v[j].w;
        cvt_sts(v, sb + S1_A0 + a_sts);
        CPWAITALL();
    }
    __syncthreads();

#pragma unroll 1
    for (int c = 0; c < T; c++) {
        const int buf = c & 1;
        int4 v[4];
        const bool more = (c + 1 < T);
        if (more) {
            const size_t ko = (size_t)(c + 1) * 64;
            const uint32_t bD = sb + boff[buf ^ 1] + b_sts;
            const char* bs = (const char*)(bsrc + ko);
#pragma unroll
            for (int j = 0; j < 4; j++) CP16(bD + j * 16, bs + j * 16);
            CPCOMMIT();
            const int4* p = (const int4*)(aptr + ko);
#pragma unroll
            for (int j = 0; j < 4; j++) v[j] = p[j];   // LDG issued; consumed after MMA
        }

        const uint32_t ab = sb + aoff[buf];
        const uint32_t bb = sb + boff[buf];
#pragma unroll
        for (int ks = 0; ks < 4; ks++) {
            uint32_t A0[4], A1[4], B[16];
            LDMX4(A0, ab + a_ld + ks * 32);
            LDMX4(A1, ab + a_ld + 16 * ROWB + ks * 32);
            LDMX4(&B[0],  bb + b_ld + ks * 32);
            LDMX4(&B[4],  bb + b_ld + 16 * ROWB + ks * 32);
            LDMX4(&B[8],  bb + b_ld + 32 * ROWB + ks * 32);
            LDMX4(&B[12], bb + b_ld + 48 * ROWB + ks * 32);
#pragma unroll
            for (int t = 0; t < 4; t++) {
                MMA(acc[0][2 * t],     A0, B[4 * t + 0], B[4 * t + 2]);
                MMA(acc[0][2 * t + 1], A0, B[4 * t + 1], B[4 * t + 3]);
                MMA(acc[1][2 * t],     A1, B[4 * t + 0], B[4 * t + 2]);
                MMA(acc[1][2 * t + 1], A1, B[4 * t + 1], B[4 * t + 3]);
            }
        }

        if (more) {
#pragma unroll
            for (int j = 0; j < 4; j++)
                deg += v[j].x + v[j].y + v[j].z + v[j].w;
            cvt_sts(v, sb + aoff[buf ^ 1] + a_sts);
            CPWAITALL();
        }
        __syncthreads();
    }

    // partial degree (4 k-segments per row within a lane quad)
    deg += __shfl_xor_sync(0xffffffffu, deg, 1);
    deg += __shfl_xor_sync(0xffffffffu, deg, 2);
    if ((tid & 3) == 0)
        g_degp[z * N_NODES + rb + arow] = (float)deg;

    // partial sums
    float* pb = g_part + ((size_t)z * N_NODES + rb) * IN_F;
#pragma unroll
    for (int mi = 0; mi < 2; mi++)
#pragma unroll
        for (int nt = 0; nt < 8; nt++) {
            const int r0 = wy * 32 + mi * 16 + (lane >> 2);
            const int cc = wx * 64 + nt * 8 + (lane & 3) * 2;
            *(float2*)(pb + (size_t)r0 * IN_F + cc) =
                make_float2(acc[mi][nt][0], acc[mi][nt][1]);
            *(float2*)(pb + (size_t)(r0 + 8) * IN_F + cc) =
                make_float2(acc[mi][nt][2], acc[mi][nt][3]);
        }
}

// =================== combine: n_x (fp16) ===================
__global__ void sage_combine(const float* __restrict__ x) {
    const int id = blockIdx.x * 256 + threadIdx.x;   // 0 .. 8192*128
    const int row = id >> 7;
    const int s   = id & 127;
    float4 v;
    int col;
    if (s < 64) {
        col = s * 4;
        const float4 p0 = *(const float4*)(g_part + (size_t)row * IN_F + col);
        const float4 p1 =
            *(const float4*)(g_part + (size_t)(N_NODES + row) * IN_F + col);
        const float inv = 1.0f / (g_degp[row] + g_degp[N_NODES + row]);
        v = make_float4((p0.x + p1.x) * inv, (p0.y + p1.y) * inv,
                        (p0.z + p1.z) * inv, (p0.w + p1.w) * inv);
    } else {
        col = IN_F + (s - 64) * 4;
        v = *(const float4*)(x + (size_t)row * IN_F + (s - 64) * 4);
    }
    __half2 h0 = __floats2half2_rn(v.x, v.y);
    __half2 h1 = __floats2half2_rn(v.z, v.w);
    uint2 H = make_uint2(*(uint32_t*)&h0, *(uint32_t*)&h1);
    *(uint2*)(g_nx + (size_t)row * TWO_F + col) = H;
}

// =================== Stage 2: out[k] = n_x @ W[k] + bias ===================
#define S2_A0   0u
#define S2_A1   18432u
#define S2_B0   36864u
#define S2_B1   73728u
#define S2_SMEM 110592

__global__ __launch_bounds__(512, 1)
void sage_out(const float* __restrict__ bias, float* __restrict__ out)
{
    extern __shared__ char smem[];
    const uint32_t sb = smem_u32(smem);
    const int tid = threadIdx.x, lane = tid & 31, wid = tid >> 5;
    const int wy = wid & 3, wx = wid >> 2;
    const int rb = blockIdx.x * 128;
    const int hd = blockIdx.y;
    const int T  = TWO_F / 64;   // 8 chunks

    const int arow = tid >> 2, aseg = tid & 3;
    const int brow = tid >> 1, bhalf = tid & 1;

    const __half* ah = g_nx + (size_t)(rb + arow) * TWO_F + aseg * 16;
    const __half* wh = g_wT + ((size_t)hd * OUT_F + brow) * TWO_F + bhalf * 32;

    const uint32_t a_sts = (uint32_t)(arow * ROWB + aseg * 32);
    const uint32_t b_sts = (uint32_t)(brow * ROWB + bhalf * 64);
    const uint32_t aoff[2] = {S2_A0, S2_A1};
    const uint32_t boff[2] = {S2_B0, S2_B1};

    const uint32_t a_ld = (uint32_t)((wy * 32 + (lane & 15)) * ROWB) + (lane & 16);
    const uint32_t b_ld = (uint32_t)((wx * 64 + (lane & 15)) * ROWB) + (lane & 16);

    float acc[2][8][4];
#pragma unroll
    for (int i = 0; i < 2; i++)
#pragma unroll
        for (int j = 0; j < 8; j++)
#pragma unroll
            for (int k = 0; k < 4; k++) acc[i][j][k] = 0.0f;

    // preload chunk 0
    {
#pragma unroll
        for (int j = 0; j < 2; j++)
            CP16(sb + S2_A0 + a_sts + j * 16, (const char*)ah + j * 16);
#pragma unroll
        for (int j = 0; j < 4; j++)
            CP16(sb + S2_B0 + b_sts + j * 16, (const char*)wh + j * 16);
        CPCOMMIT();
        CPWAITALL();
    }
    __syncthreads();

#pragma unroll 1
    for (int c = 0; c < T; c++) {
        const int buf = c & 1;
        if (c + 1 < T) {
            const size_t ko = (size_t)(c + 1) * 64;
            const uint32_t nb = buf ^ 1;
#pragma unroll
            for (int j = 0; j < 2; j++)
                CP16(sb + aoff[nb] + a_sts + j * 16, (const char*)(ah + ko) + j * 16);
#pragma unroll
            for (int j = 0; j < 4; j++)
                CP16(sb + boff[nb] + b_sts + j * 16, (const char*)(wh + ko) + j * 16);
            CPCOMMIT();
        }

        const uint32_t ab = sb + aoff[buf];
        const uint32_t bb = sb + boff[buf];
#pragma unroll
        for (int ks = 0; ks < 4; ks++) {
            uint32_t A0[4], A1[4], B[16];
            LDMX4(A0, ab + a_ld + ks * 32);
            LDMX4(A1, ab + a_ld + 16 * ROWB + ks * 32);
            LDMX4(&B[0],  bb + b_ld + ks * 32);
            LDMX4(&B[4],  bb + b_ld + 16 * ROWB + ks * 32);
            LDMX4(&B[8],  bb + b_ld + 32 * ROWB + ks * 32);
            LDMX4(&B[12], bb + b_ld + 48 * ROWB + ks * 32);
#pragma unroll
            for (int t = 0; t < 4; t++) {
                MMA(acc[0][2 * t],     A0, B[4 * t + 0], B[4 * t + 2]);
                MMA(acc[0][2 * t + 1], A0, B[4 * t + 1], B[4 * t + 3]);
                MMA(acc[1][2 * t],     A1, B[4 * t + 0], B[4 * t + 2]);
                MMA(acc[1][2 * t + 1], A1, B[4 * t + 1], B[4 * t + 3]);
            }
        }
        if (c + 1 < T) CPWAITALL();
        __syncthreads();
    }

    float* ob = out + ((size_t)hd * N_NODES + rb) * OUT_F;
#pragma unroll
    for (int mi = 0; mi < 2; mi++)
#pragma unroll
        for (int nt = 0; nt < 8; nt++) {
            const int r0 = wy * 32 + mi * 16 + (lane >> 2);
            const int cc = wx * 64 + nt * 8 + (lane & 3) * 2;
            const float2 bz = *(const float2*)(bias + cc);
            *(float2*)(ob + (size_t)r0 * OUT_F + cc) =
                make_float2(acc[mi][nt][0] + bz.x, acc[mi][nt][1] + bz.y);
            *(float2*)(ob + (size_t)(r0 + 8) * OUT_F + cc) =
                make_float2(acc[mi][nt][2] + bz.x, acc[mi][nt][3] + bz.y);
        }
}

// =================== host launch ===================
extern "C" void kernel_launch(void* const* d_in, const int* in_sizes, int n_in,
                              void* d_out, int out_size)
{
    const float* x    = nullptr;
    const int*   adj  = nullptr;
    const float* w    = nullptr;
    const float* bias = nullptr;
    for (int i = 0; i < n_in; i++) {
        switch (in_sizes[i]) {
            case N_NODES * IN_F:      x    = (const float*)d_in[i]; break;
            case N_NODES * N_NODES:   adj  = (const int*)d_in[i];   break;
            case 3 * TWO_F * OUT_F:   w    = (const float*)d_in[i]; break;
            case OUT_F:               bias = (const float*)d_in[i]; break;
            default: break;  // scalar g
        }
    }

    cudaFuncSetAttribute(sage_agg,
                         cudaFuncAttributeMaxDynamicSharedMemorySize, S1_SMEM);
    cudaFuncSetAttribute(sage_out,
                         cudaFuncAttributeMaxDynamicSharedMemorySize, S2_SMEM);

    prep_split<<<dim3(N_NODES / 32, IN_F / 32), dim3(32, 8)>>>(x);
    prep_w<<<dim3(TWO_F / 32, OUT_F / 32, 3), dim3(32, 8)>>>(w);
    sage_agg<<<dim3(N_NODES / 128, 2), 512, S1_SMEM>>>(adj);
    sage_combine<<<(N_NODES * 128) / 256, 256>>>(x);
    sage_out<<<dim3(N_NODES / 128, 3), 512, S2_SMEM>>>(bias, (float*)d_out);
}